// round 1
// baseline (speedup 1.0000x reference)
#include <cuda_runtime.h>

#define BQ 256
#define DD 256
#define NBANK 100000
#define TN 64
#define KC 32
#define NUM_TILES ((NBANK + TN - 1) / TN)

// Scratch (allocation-free rule: __device__ globals)
__device__ float              g_b2[NBANK];
__device__ unsigned long long g_bestP[BQ];
__device__ unsigned long long g_bestF[BQ];

// ---------------------------------------------------------------------------
// Kernel 1: row squared-norms of the bank. One warp per row.
// ---------------------------------------------------------------------------
__global__ void b2_kernel(const float* __restrict__ bank) {
    int row = blockIdx.x * 8 + (threadIdx.x >> 5);
    if (row >= NBANK) return;
    int lane = threadIdx.x & 31;
    const float* r = bank + (size_t)row * DD;
    float s = 0.f;
#pragma unroll
    for (int t = 0; t < DD / 32; ++t) {
        float v = r[lane + 32 * t];
        s = fmaf(v, v, s);
    }
#pragma unroll
    for (int o = 16; o; o >>= 1) s += __shfl_xor_sync(0xffffffffu, s, o);
    if (lane == 0) g_b2[row] = s;
}

// ---------------------------------------------------------------------------
// Kernel 2: reset global best arrays (must happen every launch — graph replays)
// ---------------------------------------------------------------------------
__global__ void init_kernel() {
    int t = threadIdx.x;
    if (t < BQ) {
        g_bestP[t] = ~0ULL;
        g_bestF[t] = ~0ULL;
    }
}

// Order-preserving float -> u32 encoding, packed with index.
// Smaller score -> smaller u64; ties broken by smaller index (matches argmin).
__device__ __forceinline__ unsigned long long encode(float f, int n) {
    unsigned u = __float_as_uint(f);
    u = (u & 0x80000000u) ? ~u : (u | 0x80000000u);
    return ((unsigned long long)u << 32) | (unsigned)n;
}

// ---------------------------------------------------------------------------
// Kernel 3: fused GEMM (score = b2[n] - 2*dot) + masked dual argmin.
// One CTA per TN=64 bank rows. 256 threads, 8x8 register tile each:
//   thread (tb = tid&31, tn = tid>>5) owns b = tb+32*i (i<8), n = n0+tn*8+j (j<8).
// ---------------------------------------------------------------------------
#define SMEM_BYTES (2*BQ*8 /*red*/ + TN*DD*4 /*Bs*/ + KC*(BQ+1)*4 /*Qs*/ \
                    + TN*4 /*b2s*/ + TN*4 + TN*4 /*labels*/ + BQ*4 + BQ*4 /*cid,gt*/)

__global__ void __launch_bounds__(256) main_kernel(
    const float* __restrict__ feat, const float* __restrict__ bank,
    const int* __restrict__ cluL, const int* __restrict__ clsL,
    const int* __restrict__ cid, const int* __restrict__ gt)
{
    extern __shared__ unsigned char smraw[];
    unsigned long long* redP = (unsigned long long*)smraw;      // [BQ]
    unsigned long long* redF = redP + BQ;                       // [BQ]
    float* Bs  = (float*)(redF + BQ);                           // [TN][DD]
    float* Qs  = Bs + TN * DD;                                  // [KC][BQ+1] (pad)
    float* b2s = Qs + KC * (BQ + 1);                            // [TN]
    int*   sClu = (int*)(b2s + TN);                             // [TN]
    int*   sCls = sClu + TN;                                    // [TN]
    int*   sCid = sCls + TN;                                    // [BQ]
    int*   sGt  = sCid + BQ;                                    // [BQ]

    const int tid = threadIdx.x;
    const int n0  = blockIdx.x * TN;

    if (tid < BQ) {
        redP[tid] = ~0ULL;
        redF[tid] = ~0ULL;
        sCid[tid] = cid[tid];
        sGt[tid]  = gt[tid];
    }
    if (tid < TN) {
        int n = n0 + tid;
        bool v = (n < NBANK);
        sClu[tid] = v ? cluL[n] : -1;
        sCls[tid] = v ? clsL[n] : 0x7fffffff;
        b2s[tid]  = v ? g_b2[n] : 0.f;
    }
    // Load bank tile [TN][DD] via float4, coalesced along k.
    {
        const float4* b4  = (const float4*)bank;
        float4*       Bs4 = (float4*)Bs;
        for (int i = tid; i < TN * (DD / 4); i += 256) {
            int n = n0 + i / (DD / 4);
            Bs4[i] = (n < NBANK) ? b4[(size_t)n * (DD / 4) + (i % (DD / 4))]
                                 : make_float4(0.f, 0.f, 0.f, 0.f);
        }
    }

    float acc[8][8];
#pragma unroll
    for (int i = 0; i < 8; i++)
#pragma unroll
        for (int j = 0; j < 8; j++) acc[i][j] = 0.f;

    const int tb = tid & 31;
    const int tn = tid >> 5;

    for (int kc = 0; kc < DD; kc += KC) {
        __syncthreads();  // prior compute done (and initial loads visible)
        // Stage query chunk: Qs[k][b] = feat[b][kc+k]; coalesced global reads,
        // conflict-free padded smem stores (stride BQ+1).
        for (int i = tid; i < KC * BQ; i += 256) {
            int b = i >> 5;        // KC == 32
            int k = i & 31;
            Qs[k * (BQ + 1) + b] = feat[b * DD + kc + k];
        }
        __syncthreads();
#pragma unroll
        for (int k = 0; k < KC; ++k) {
            float af[8], bf[8];
#pragma unroll
            for (int j = 0; j < 8; j++) bf[j] = Bs[(tn * 8 + j) * DD + kc + k];  // broadcast
#pragma unroll
            for (int i = 0; i < 8; i++) af[i] = Qs[k * (BQ + 1) + tb + 32 * i];  // conflict-free
#pragma unroll
            for (int i = 0; i < 8; i++)
#pragma unroll
                for (int j = 0; j < 8; j++)
                    acc[i][j] = fmaf(af[i], bf[j], acc[i][j]);
        }
    }

    // Masked dual argmin: per-thread reduce over its 8 n's, shared atomics per b.
#pragma unroll
    for (int i = 0; i < 8; i++) {
        int b = tb + 32 * i;
        int gtb = sGt[b], cib = sCid[b];
        unsigned long long bp = ~0ULL, bfv = ~0ULL;
#pragma unroll
        for (int j = 0; j < 8; j++) {
            int jj = tn * 8 + j;
            int n = n0 + jj;
            if (n >= NBANK) continue;
            if (sCls[jj] == gtb) continue;          // must be different class
            float score = fmaf(-2.f, acc[i][j], b2s[jj]);
            unsigned long long e = encode(score, n);
            if (e < bfv) bfv = e;
            if (sClu[jj] == cib && e < bp) bp = e;
        }
        if (bfv != ~0ULL) atomicMin(&redF[b], bfv);
        if (bp  != ~0ULL) atomicMin(&redP[b], bp);
    }
    __syncthreads();
    if (tid < BQ) {
        unsigned long long p = redP[tid], f = redF[tid];
        if (p != ~0ULL) atomicMin(&g_bestP[tid], p);
        if (f != ~0ULL) atomicMin(&g_bestF[tid], f);
    }
}

// ---------------------------------------------------------------------------
// Kernel 4: select primary-else-fallback, gather winning bank rows to output.
// ---------------------------------------------------------------------------
__global__ void gather_kernel(const float* __restrict__ bank, float* __restrict__ out) {
    int b = blockIdx.x;
    unsigned long long e = g_bestP[b];
    if (e == ~0ULL) e = g_bestF[b];
    int idx = (e == ~0ULL) ? 0 : (int)(unsigned)(e & 0xffffffffu);
    const float4* src = (const float4*)(bank + (size_t)idx * DD);
    float4*       dst = (float4*)(out + (size_t)b * DD);
    dst[threadIdx.x] = src[threadIdx.x];
}

// ---------------------------------------------------------------------------
extern "C" void kernel_launch(void* const* d_in, const int* in_sizes, int n_in,
                              void* d_out, int out_size) {
    const float* feature = (const float*)d_in[0];
    const float* bank    = (const float*)d_in[1];
    const int*   cluL    = (const int*)d_in[2];
    const int*   clsL    = (const int*)d_in[3];
    const int*   cid     = (const int*)d_in[4];
    const int*   gtl     = (const int*)d_in[5];

    cudaFuncSetAttribute(main_kernel,
                         cudaFuncAttributeMaxDynamicSharedMemorySize, SMEM_BYTES);

    b2_kernel<<<(NBANK + 7) / 8, 256>>>(bank);
    init_kernel<<<1, 256>>>();
    main_kernel<<<NUM_TILES, 256, SMEM_BYTES>>>(feature, bank, cluL, clsL, cid, gtl);
    gather_kernel<<<BQ, 64>>>(bank, (float*)d_out);
}

// round 2
// speedup vs baseline: 1.0663x; 1.0663x over previous
#include <cuda_runtime.h>

#define BQ 256
#define DD 256
#define NBANK 100000
#define TN 64
#define KC 32
#define QP 258                    // Qs row stride (floats): even (LDS.64 align), %32==2 (no store conflicts)
#define NUM_TILES ((NBANK + TN - 1) / TN)
#define NCHUNK (DD / KC)

typedef unsigned long long ull;

__device__ ull g_bestP[BQ];
__device__ ull g_bestF[BQ];

// packed f32x2 FMA: d.lo += a.lo*b.lo; d.hi += a.hi*b.hi  (exact IEEE fp32 fma per lane)
#define FMA2(d, a, b) asm("fma.rn.f32x2 %0, %1, %2, %0;" : "+l"(d) : "l"(a), "l"(b))

__device__ __forceinline__ ull dup_f(float f) {
    unsigned u = __float_as_uint(f);
    return (ull)u | ((ull)u << 32);
}

// Order-preserving float->u32, packed with index. Smaller score -> smaller u64;
// ties broken by smaller index (matches jnp.argmin first-occurrence).
__device__ __forceinline__ ull encode(float f, int n) {
    unsigned u = __float_as_uint(f);
    u = (u & 0x80000000u) ? ~u : (u | 0x80000000u);
    return ((ull)u << 32) | (unsigned)n;
}

__global__ void init_kernel() {
    int t = threadIdx.x;
    if (t < BQ) { g_bestP[t] = ~0ULL; g_bestF[t] = ~0ULL; }
}

// ---------------------------------------------------------------------------
// Fused: bank-tile load + row norms + GEMM (f32x2) + masked dual argmin.
// CTA = TN=64 bank rows. 256 threads. Thread (tb=tid&31, tn=tid>>5) owns
// b = 2*tb + 64*i + h (i<4, h<2) and n = n0 + tn*8 + j (j<8).
// ---------------------------------------------------------------------------
#define SMEM_BYTES (2*BQ*8 /*red*/ + TN*DD*8 /*Bs2 dup pairs*/ + 2*KC*QP*4 /*Qs dbl*/ \
                    + TN*4 /*b2s*/ + 2*TN*4 /*labels*/ + 2*BQ*4 /*cid,gt*/)

__global__ void __launch_bounds__(256) main_kernel(
    const float* __restrict__ feat, const float* __restrict__ bank,
    const int* __restrict__ cluL, const int* __restrict__ clsL,
    const int* __restrict__ cid, const int* __restrict__ gt)
{
    extern __shared__ unsigned char smraw[];
    ull*   redP = (ull*)smraw;                     // [BQ]
    ull*   redF = redP + BQ;                       // [BQ]
    ull*   Bs2  = redF + BQ;                       // [TN][DD] duplicated pairs
    float* Qs   = (float*)(Bs2 + TN * DD);         // [2][KC][QP]
    float* b2s  = Qs + 2 * KC * QP;                // [TN]
    int*   sClu = (int*)(b2s + TN);                // [TN]
    int*   sCls = sClu + TN;                       // [TN]
    int*   sCid = sCls + TN;                       // [BQ]
    int*   sGt  = sCid + BQ;                       // [BQ]

    const int tid = threadIdx.x;
    const int n0  = blockIdx.x * TN;
    const int tb  = tid & 31;
    const int tn  = tid >> 5;

    if (tid < BQ) {
        redP[tid] = ~0ULL; redF[tid] = ~0ULL;
        sCid[tid] = cid[tid]; sGt[tid] = gt[tid];
    }
    if (tid < TN) {
        int n = n0 + tid;
        bool v = (n < NBANK);
        sClu[tid] = v ? cluL[n] : -1;
        sCls[tid] = v ? clsL[n] : 0x7fffffff;
    }

    // Load bank tile coalesced (float4), store duplicated pairs.
    {
        const float4* b4 = (const float4*)bank;
#pragma unroll
        for (int r = 0; r < TN * (DD / 4) / 256; ++r) {
            int i  = tid + 256 * r;
            int n  = i >> 6;                 // DD/4 == 64
            int kq = i & 63;
            float4 v = (n0 + n < NBANK) ? b4[(size_t)(n0 + n) * (DD / 4) + kq]
                                        : make_float4(0.f, 0.f, 0.f, 0.f);
            ull* dst = Bs2 + (n * DD + 4 * kq);
            dst[0] = dup_f(v.x); dst[1] = dup_f(v.y);
            dst[2] = dup_f(v.z); dst[3] = dup_f(v.w);
        }
    }
    // Stage query chunk 0 (coalesced LDG; QP=258 -> conflict-light STS).
    {
#pragma unroll
        for (int r = 0; r < KC * BQ / 256; ++r) {
            int e = tid + 256 * r;
            int k = e & 31, b = e >> 5;
            Qs[k * QP + b] = feat[b * DD + k];
        }
    }
    __syncthreads();

    // Row norms from smem tile: warp w handles rows 8w..8w+7.
    {
        int lane = tid & 31, w = tid >> 5;
#pragma unroll
        for (int rr = 0; rr < 8; ++rr) {
            int n = w * 8 + rr;
            float s = 0.f;
#pragma unroll
            for (int t = 0; t < DD / 32; ++t) {
                float v = __uint_as_float((unsigned)Bs2[n * DD + lane + 32 * t]);
                s = fmaf(v, v, s);
            }
#pragma unroll
            for (int o = 16; o; o >>= 1) s += __shfl_xor_sync(0xffffffffu, s, o);
            if (lane == 0) b2s[n] = s;
        }
    }
    __syncthreads();

    ull acc2[4][8];
#pragma unroll
    for (int i = 0; i < 4; i++)
#pragma unroll
        for (int j = 0; j < 8; j++) acc2[i][j] = 0ULL;

    const int aoff = 2 * tb;

#pragma unroll 1
    for (int c = 0; c < NCHUNK; ++c) {
        // Stage next chunk into the other buffer (LDGs overlap compute below).
        if (c + 1 < NCHUNK) {
            float* qn = Qs + ((c + 1) & 1) * KC * QP;
            int kc2 = (c + 1) * KC;
#pragma unroll
            for (int r = 0; r < KC * BQ / 256; ++r) {
                int e = tid + 256 * r;
                int k = e & 31, b = e >> 5;
                qn[k * QP + b] = feat[b * DD + kc2 + k];
            }
        }
        const float* qb = Qs + (c & 1) * KC * QP;
        const int kc = c * KC;
#pragma unroll
        for (int k = 0; k < KC; ++k) {
            ull a2[4];
#pragma unroll
            for (int i = 0; i < 4; i++)
                a2[i] = *(const ull*)(qb + k * QP + aoff + 64 * i);   // LDS.64, conflict-free
#pragma unroll
            for (int j = 0; j < 8; j++) {
                ull bv = Bs2[(tn * 8 + j) * DD + kc + k];             // LDS.64 broadcast
#pragma unroll
                for (int i = 0; i < 4; i++) FMA2(acc2[i][j], a2[i], bv);
            }
        }
        __syncthreads();
    }

    // Masked dual argmin.
#pragma unroll
    for (int i = 0; i < 4; i++) {
#pragma unroll
        for (int h = 0; h < 2; h++) {
            int b = aoff + 64 * i + h;
            int gtb = sGt[b], cib = sCid[b];
            ull bp = ~0ULL, bf = ~0ULL;
#pragma unroll
            for (int j = 0; j < 8; j++) {
                int jj = tn * 8 + j;
                int n = n0 + jj;
                if (n >= NBANK) continue;
                if (sCls[jj] == gtb) continue;
                unsigned ubits = h ? (unsigned)(acc2[i][j] >> 32) : (unsigned)acc2[i][j];
                float dot = __uint_as_float(ubits);
                float score = fmaf(-2.f, dot, b2s[jj]);
                ull e = encode(score, n);
                if (e < bf) bf = e;
                if (sClu[jj] == cib && e < bp) bp = e;
            }
            if (bf != ~0ULL) atomicMin(&redF[b], bf);
            if (bp != ~0ULL) atomicMin(&redP[b], bp);
        }
    }
    __syncthreads();
    if (tid < BQ) {
        ull p = redP[tid], f = redF[tid];
        if (p != ~0ULL) atomicMin(&g_bestP[tid], p);
        if (f != ~0ULL) atomicMin(&g_bestF[tid], f);
    }
}

// ---------------------------------------------------------------------------
__global__ void gather_kernel(const float* __restrict__ bank, float* __restrict__ out) {
    int b = blockIdx.x;
    ull e = g_bestP[b];
    if (e == ~0ULL) e = g_bestF[b];
    int idx = (e == ~0ULL) ? 0 : (int)(unsigned)(e & 0xffffffffu);
    const float4* src = (const float4*)(bank + (size_t)idx * DD);
    float4*       dst = (float4*)(out + (size_t)b * DD);
    dst[threadIdx.x] = src[threadIdx.x];
}

// ---------------------------------------------------------------------------
extern "C" void kernel_launch(void* const* d_in, const int* in_sizes, int n_in,
                              void* d_out, int out_size) {
    const float* feature = (const float*)d_in[0];
    const float* bank    = (const float*)d_in[1];
    const int*   cluL    = (const int*)d_in[2];
    const int*   clsL    = (const int*)d_in[3];
    const int*   cid     = (const int*)d_in[4];
    const int*   gtl     = (const int*)d_in[5];

    cudaFuncSetAttribute(main_kernel,
                         cudaFuncAttributeMaxDynamicSharedMemorySize, SMEM_BYTES);

    init_kernel<<<1, 256>>>();
    main_kernel<<<NUM_TILES, 256, SMEM_BYTES>>>(feature, bank, cluL, clsL, cid, gtl);
    gather_kernel<<<BQ, 64>>>(bank, (float*)d_out);
}

// round 4
// speedup vs baseline: 1.8989x; 1.7809x over previous
#include <cuda_runtime.h>
#include <cuda_bf16.h>

#define BQ 256
#define DD 256
#define NBANK 100000
#define TN 128
#define NUM_TILES ((NBANK + TN - 1) / TN)
#define NCH 8            // K chunks of 32
#define KCH 32

typedef unsigned long long ull;
typedef unsigned int u32;

// --------------- device scratch (no allocation allowed) ---------------------
__device__ ull   g_bestP[BQ];
__device__ ull   g_bestF[BQ];
__device__ uint4 g_Q[NCH][2][BQ][4];   // pre-split queries [chunk][hi/lo][q][4x16B]

// --------------- smem layout (bytes) ----------------------------------------
#define SB 528                               // bank row stride (256 bf16 + 8 pad)
#define SQ 80                                // query chunk row stride (32 bf16 + 8 pad)
#define OFF_BH   0
#define OFF_BL   (OFF_BH + TN * SB)          // 67584
#define OFF_Q    (OFF_BL + TN * SB)          // 135168: [2 buf][2 split][256 q][80B]
#define OFF_RED  (OFF_Q + 2 * 2 * BQ * SQ)   // 217088: redP[256], redF[256]
#define OFF_B2S  (OFF_RED + 2 * BQ * 8)      // 221184
#define OFF_SCLU (OFF_B2S + 512)
#define OFF_SCLS (OFF_SCLU + 512)
#define OFF_SCID (OFF_SCLS + 512)
#define OFF_SGT  (OFF_SCID + 1024)
#define SMEM_TOTAL (OFF_SGT + 1024)          // 224768 <= 227KB

// --------------- helpers ------------------------------------------------------
__device__ __forceinline__ u32 smem_u32(const void* p) {
    u32 a;
    asm("{ .reg .u64 t; cvta.to.shared.u64 t, %1; cvt.u32.u64 %0, t; }" : "=r"(a) : "l"(p));
    return a;
}

#define LDSM_X4(r, addr) \
    asm volatile("ldmatrix.sync.aligned.m8n8.x4.shared.b16 {%0,%1,%2,%3}, [%4];" \
        : "=r"((r)[0]), "=r"((r)[1]), "=r"((r)[2]), "=r"((r)[3]) : "r"(addr))

#define MMA16816(d, a, b0, b1) \
    asm volatile("mma.sync.aligned.m16n8k16.row.col.f32.bf16.bf16.f32 " \
        "{%0,%1,%2,%3}, {%4,%5,%6,%7}, {%8,%9}, {%0,%1,%2,%3};" \
        : "+f"((d)[0]), "+f"((d)[1]), "+f"((d)[2]), "+f"((d)[3]) \
        : "r"((a)[0]), "r"((a)[1]), "r"((a)[2]), "r"((a)[3]), "r"(b0), "r"(b1))

#define CP_ASYNC16(dst, src) \
    asm volatile("cp.async.cg.shared.global [%0], [%1], 16;" :: "r"(dst), "l"(src) : "memory")
#define CP_COMMIT() asm volatile("cp.async.commit_group;" ::: "memory")
#define CP_WAIT0()  asm volatile("cp.async.wait_group 0;" ::: "memory")

// order-preserving float->u32 packed with index; ties -> lower index (argmin)
__device__ __forceinline__ ull encode(float f, int n) {
    u32 u = __float_as_uint(f);
    u = (u & 0x80000000u) ? ~u : (u | 0x80000000u);
    return ((ull)u << 32) | (u32)n;
}

__device__ __forceinline__ void split2(float a0, float a1, u32& H, u32& L) {
    __nv_bfloat16 h0 = __float2bfloat16(a0);
    __nv_bfloat16 h1 = __float2bfloat16(a1);
    __nv_bfloat16 l0 = __float2bfloat16(a0 - __bfloat162float(h0));
    __nv_bfloat16 l1 = __float2bfloat16(a1 - __bfloat162float(h1));
    H = (u32)__bfloat16_as_ushort(h0) | ((u32)__bfloat16_as_ushort(h1) << 16);
    L = (u32)__bfloat16_as_ushort(l0) | ((u32)__bfloat16_as_ushort(l1) << 16);
}

// ---------------------------------------------------------------------------
// prep: reset best arrays, split queries into bf16 hi/lo chunk images.
// ---------------------------------------------------------------------------
__global__ void prep_kernel(const float* __restrict__ feat) {
    int q = threadIdx.x;
    g_bestP[q] = ~0ULL;
    g_bestF[q] = ~0ULL;
    const float* row = feat + q * DD;
#pragma unroll
    for (int c = 0; c < NCH; ++c) {
#pragma unroll
        for (int i = 0; i < 4; ++i) {       // 4 x 16B (8 bf16) per 32-k chunk
            u32 H[4], L[4];
#pragma unroll
            for (int e = 0; e < 8; e += 2) {
                int k = c * KCH + i * 8 + e;
                split2(row[k], row[k + 1], H[e >> 1], L[e >> 1]);
            }
            g_Q[c][0][q][i] = make_uint4(H[0], H[1], H[2], H[3]);
            g_Q[c][1][q][i] = make_uint4(L[0], L[1], L[2], L[3]);
        }
    }
}

// ---------------------------------------------------------------------------
__device__ __forceinline__ void stage_chunk(u32 smb, int buf, int c, int tid) {
    const uint4* srcH = &g_Q[c][0][tid][0];
    const uint4* srcL = &g_Q[c][1][tid][0];
    u32 dH = smb + OFF_Q + (u32)((buf * 2 + 0) * BQ + tid) * SQ;
    u32 dL = smb + OFF_Q + (u32)((buf * 2 + 1) * BQ + tid) * SQ;
#pragma unroll
    for (int i = 0; i < 4; ++i) {
        CP_ASYNC16(dH + 16 * i, srcH + i);
        CP_ASYNC16(dL + 16 * i, srcL + i);
    }
}

// ---------------------------------------------------------------------------
// main: 128 bank rows x 256 queries per CTA; 3-split bf16 HMMA GEMM + fused
// row norms + masked dual argmin.
// ---------------------------------------------------------------------------
__global__ void __launch_bounds__(256, 1) main_kernel(
    const float* __restrict__ bank,
    const int* __restrict__ cluL, const int* __restrict__ clsL,
    const int* __restrict__ cid,  const int* __restrict__ gt)
{
    extern __shared__ char sm[];
    const u32 smb  = smem_u32(sm);
    const int tid  = threadIdx.x;
    const int lane = tid & 31;
    const int w    = tid >> 5;
    const int n0   = blockIdx.x * TN;

    ull*   redP = (ull*)(sm + OFF_RED);
    ull*   redF = redP + BQ;
    float* b2s  = (float*)(sm + OFF_B2S);
    int*   sClu = (int*)(sm + OFF_SCLU);
    int*   sCls = (int*)(sm + OFF_SCLS);
    int*   sCid = (int*)(sm + OFF_SCID);
    int*   sGt  = (int*)(sm + OFF_SGT);

    redP[tid] = ~0ULL;
    redF[tid] = ~0ULL;
    sCid[tid] = cid[tid];
    sGt[tid]  = gt[tid];
    if (tid < TN) {
        int n = n0 + tid;
        bool v = (n < NBANK);
        sClu[tid] = v ? cluL[n] : -1;
        sCls[tid] = v ? clsL[n] : 0x7fffffff;
    }

    // Kick off async staging of Q chunk 0, then convert the bank tile (overlap).
    stage_chunk(smb, 0, 0, tid);
    CP_COMMIT();

    // Bank fp32 -> (bh, bl) bf16 full-K smem tiles + fused row norms.
    {
        const float4* b4 = (const float4*)bank;
#pragma unroll
        for (int it = 0; it < 16; ++it) {
            int g = it * 256 + tid;
            int n = g >> 5, o = g & 31;                 // row, octet(8 cols)
            int gn = n0 + n;
            float4 v0 = make_float4(0.f, 0.f, 0.f, 0.f), v1 = v0;
            if (gn < NBANK) {
                v0 = b4[(size_t)gn * (DD / 4) + 2 * o];
                v1 = b4[(size_t)gn * (DD / 4) + 2 * o + 1];
            }
            float vv[8] = {v0.x, v0.y, v0.z, v0.w, v1.x, v1.y, v1.z, v1.w};
            u32 H[4], L[4];
            float s = 0.f;
#pragma unroll
            for (int e = 0; e < 8; e += 2) {
                s = fmaf(vv[e], vv[e], s);
                s = fmaf(vv[e + 1], vv[e + 1], s);
                split2(vv[e], vv[e + 1], H[e >> 1], L[e >> 1]);
            }
            *(uint4*)(sm + OFF_BH + n * SB + o * 16) = make_uint4(H[0], H[1], H[2], H[3]);
            *(uint4*)(sm + OFF_BL + n * SB + o * 16) = make_uint4(L[0], L[1], L[2], L[3]);
#pragma unroll
            for (int off = 16; off; off >>= 1) s += __shfl_xor_sync(0xffffffffu, s, off);
            if (lane == 0) b2s[n] = s;
        }
    }

    CP_WAIT0();
    __syncthreads();

    // Warp tiling: 4 q-groups x 2 n-halves. 64q x 64n per warp.
    const int q0 = (w & 3) * 64;
    const int nh = (w >> 2) * 64;

    float acc[4][8][4];
#pragma unroll
    for (int mi = 0; mi < 4; mi++)
#pragma unroll
        for (int nt = 0; nt < 8; nt++)
#pragma unroll
            for (int r = 0; r < 4; r++) acc[mi][nt][r] = 0.f;

    // Per-lane ldmatrix address components.
    const u32 aRowOff = (u32)(q0 + (lane & 15)) * SQ + (u32)(lane >> 4) * 16;
    const int bRow    = nh + ((lane >> 4) & 1) * 8 + (lane & 7);   // + pair*16
    const u32 bColH   = ((lane >> 3) & 1) * 8;                     // k half within step

#pragma unroll 1
    for (int c = 0; c < NCH; ++c) {
        if (c < NCH - 1) { stage_chunk(smb, (c + 1) & 1, c + 1, tid); CP_COMMIT(); }
        const int buf = c & 1;
        const u32 qH = smb + OFF_Q + (u32)((buf * 2 + 0) * BQ) * SQ + aRowOff;
        const u32 qL = qH + (u32)BQ * SQ;
#pragma unroll
        for (int kk = 0; kk < KCH; kk += 16) {
            u32 aH[4][4];
#pragma unroll
            for (int mi = 0; mi < 4; mi++) LDSM_X4(aH[mi], qH + mi * 16 * SQ + kk * 2);

            u32 bB[16];
            const u32 kbyteH = (u32)(c * KCH + kk) * 2 + bColH * 2;
#pragma unroll
            for (int p = 0; p < 4; p++)
                LDSM_X4(&bB[4 * p], smb + OFF_BH + (u32)(bRow + p * 16) * SB + kbyteH);
#pragma unroll
            for (int mi = 0; mi < 4; mi++)
#pragma unroll
                for (int nt = 0; nt < 8; nt++)
                    MMA16816(acc[mi][nt], aH[mi], bB[2 * nt], bB[2 * nt + 1]);

            u32 aL[4][4];
#pragma unroll
            for (int mi = 0; mi < 4; mi++) LDSM_X4(aL[mi], qL + mi * 16 * SQ + kk * 2);
#pragma unroll
            for (int mi = 0; mi < 4; mi++)
#pragma unroll
                for (int nt = 0; nt < 8; nt++)
                    MMA16816(acc[mi][nt], aL[mi], bB[2 * nt], bB[2 * nt + 1]);

#pragma unroll
            for (int p = 0; p < 4; p++)
                LDSM_X4(&bB[4 * p], smb + OFF_BL + (u32)(bRow + p * 16) * SB + kbyteH);
#pragma unroll
            for (int mi = 0; mi < 4; mi++)
#pragma unroll
                for (int nt = 0; nt < 8; nt++)
                    MMA16816(acc[mi][nt], aH[mi], bB[2 * nt], bB[2 * nt + 1]);
        }
        if (c < NCH - 1) { CP_WAIT0(); __syncthreads(); }
    }

    // ---- epilogue: masked dual argmin from HMMA fragments ----
    {
        const int jb = nh + 2 * (lane & 3);
        float b2r[16]; int clsr[16], clur[16]; bool val[16];
#pragma unroll
        for (int ni = 0; ni < 8; ni++)
#pragma unroll
            for (int h = 0; h < 2; h++) {
                int j = jb + 8 * ni + h, x = ni * 2 + h;
                b2r[x]  = b2s[j];
                clsr[x] = sCls[j];
                clur[x] = sClu[j];
                val[x]  = (n0 + j) < NBANK;
            }
#pragma unroll
        for (int mi = 0; mi < 4; mi++) {
#pragma unroll
            for (int half = 0; half < 2; half++) {
                int r = q0 + mi * 16 + (lane >> 2) + 8 * half;
                int gtq = sGt[r], ciq = sCid[r];
                ull bp = ~0ULL, bf = ~0ULL;
#pragma unroll
                for (int ni = 0; ni < 8; ni++)
#pragma unroll
                    for (int h = 0; h < 2; h++) {
                        int x = ni * 2 + h;
                        if (!val[x] || clsr[x] == gtq) continue;
                        float score = fmaf(-2.f, acc[mi][ni][half * 2 + h], b2r[x]);
                        ull e = encode(score, n0 + jb + 8 * ni + h);
                        if (e < bf) bf = e;
                        if (clur[x] == ciq && e < bp) bp = e;
                    }
#pragma unroll
                for (int o = 1; o <= 2; o <<= 1) {
                    ull tp = __shfl_xor_sync(0xffffffffu, bp, o);
                    ull tf = __shfl_xor_sync(0xffffffffu, bf, o);
                    if (tp < bp) bp = tp;
                    if (tf < bf) bf = tf;
                }
                if ((lane & 3) == 0) {
                    if (bp != ~0ULL) atomicMin(&redP[r], bp);
                    if (bf != ~0ULL) atomicMin(&redF[r], bf);
                }
            }
        }
    }
    __syncthreads();
    {
        ull p = redP[tid], f = redF[tid];
        if (p != ~0ULL) atomicMin(&g_bestP[tid], p);
        if (f != ~0ULL) atomicMin(&g_bestF[tid], f);
    }
}

// ---------------------------------------------------------------------------
__global__ void gather_kernel(const float* __restrict__ bank, float* __restrict__ out) {
    int b = blockIdx.x;
    ull e = g_bestP[b];
    if (e == ~0ULL) e = g_bestF[b];
    int idx = (e == ~0ULL) ? 0 : (int)(u32)(e & 0xffffffffu);
    const float4* src = (const float4*)(bank + (size_t)idx * DD);
    float4*       dst = (float4*)(out + (size_t)b * DD);
    dst[threadIdx.x] = src[threadIdx.x];
}

__global__ void noop_kernel() {}   // pads launch count so ncu -s 5 lands on main_kernel

// ---------------------------------------------------------------------------
extern "C" void kernel_launch(void* const* d_in, const int* in_sizes, int n_in,
                              void* d_out, int out_size) {
    const float* feature = (const float*)d_in[0];
    const float* bank    = (const float*)d_in[1];
    const int*   cluL    = (const int*)d_in[2];
    const int*   clsL    = (const int*)d_in[3];
    const int*   cid     = (const int*)d_in[4];
    const int*   gtl     = (const int*)d_in[5];

    cudaFuncSetAttribute(main_kernel,
                         cudaFuncAttributeMaxDynamicSharedMemorySize, SMEM_TOTAL);

    prep_kernel<<<1, 256>>>(feature);
    main_kernel<<<NUM_TILES, 256, SMEM_TOTAL>>>(bank, cluL, clsL, cid, gtl);
    gather_kernel<<<BQ, 64>>>(bank, (float*)d_out);
    noop_kernel<<<1, 32>>>();
}